// round 8
// baseline (speedup 1.0000x reference)
#include <cuda_runtime.h>
#include <math.h>

#define VOCAB 50000
#define EMB 50
#define B 256
#define S 2048
#define L1OUT 2054          // conv1 output length
#define SEG 514             // outputs per segment CTA (4 segs: 514,514,514,512)
#define WINR 520            // T rows per segment window (SEG + 6 halo)
#define FULL 0xffffffffu

// Device-global scratch
__device__ __align__(16) float g_T[VOCAB * 8];   // T[v][0..6]
__device__ unsigned g_cand_u[B * 32];            // per-segment top-8 values (monotone u32)
__device__ int      g_cand_t[B * 32];            // per-segment top-8 global indices
__device__ float    g_part[B];                   // per-row dense output
__device__ unsigned g_ctr = 0;                   // last-CTA counter (wraps -> self-reset)

// Order-preserving float -> u32 map (u32 compare == float compare)
__device__ __forceinline__ unsigned fmono(float f) {
    unsigned u = __float_as_uint(f);
    return (u & 0x80000000u) ? ~u : (u | 0x80000000u);
}

// ---------------------------------------------------------------------------
// Kernel A: T[v][kw] = dot(emb[v], wmean[kw]); 128 rows/CTA, coalesced staging
// ---------------------------------------------------------------------------
__global__ void __launch_bounds__(128) buildT_kernel(
    const float* __restrict__ emb, const float* __restrict__ W1) {
    __shared__ float se[128 * 51];
    __shared__ float wm[7 * 50];

    const int tid  = threadIdx.x;
    const int base = blockIdx.x * 128;
    const int nrows = min(128, VOCAB - base);

    for (int i = tid; i < 350; i += 128) {
        float s = 0.f;
        #pragma unroll
        for (int c = 0; c < 6; c++) s += W1[i * 6 + c];
        wm[i] = s * (1.f / 6.f);
    }
    const float2* e2 = (const float2*)(emb + (size_t)base * EMB);
    for (int i = tid; i < nrows * 25; i += 128) {
        int row = i / 25;
        int c2  = i - row * 25;
        float2 v = e2[row * 25 + c2];
        se[row * 51 + 2 * c2]     = v.x;
        se[row * 51 + 2 * c2 + 1] = v.y;
    }
    __syncthreads();

    if (tid >= nrows) return;
    const float* er = se + tid * 51;
    float acc[7] = {0.f, 0.f, 0.f, 0.f, 0.f, 0.f, 0.f};
    #pragma unroll 10
    for (int cin = 0; cin < EMB; cin++) {
        float e = er[cin];
        #pragma unroll
        for (int kw = 0; kw < 7; kw++) acc[kw] += e * wm[kw * EMB + cin];
    }
    float4* d = (float4*)(g_T + (size_t)(base + tid) * 8);
    d[0] = make_float4(acc[0], acc[1], acc[2], acc[3]);
    d[1] = make_float4(acc[4], acc[5], acc[6], 0.f);
}

// ---------------------------------------------------------------------------
// Kernel B1: 4 CTAs per row (grid 1024), 256 thr. Each CTA: stage 520-token
// window, gather T, 514 excitements (zero-padded halo), segment top-8 -> gmem.
// ---------------------------------------------------------------------------
__global__ void __launch_bounds__(256) topk_seg_kernel(const int* __restrict__ x) {
    __shared__ int      stok[WINR];          // window tokens (-1 = out of range)
    __shared__ float    sTl[WINR * 7];       // T rows, stride 7 (zero for pad rows)
    __shared__ unsigned cu_s[64];
    __shared__ int      ct_s[64];

    const int tid  = threadIdx.x;
    const int lane = tid & 31;
    const int wid  = tid >> 5;
    const int row  = blockIdx.x >> 2;
    const int seg  = blockIdx.x & 3;
    const int t0   = seg * SEG;
    const int len  = min(SEG, L1OUT - t0);   // 514 or 512
    const int* xr  = x + (size_t)row * S;

    // ---- stage tokens for window q in [0, WINR): p = q + t0 - 6
    #pragma unroll
    for (int k = 0; k < 3; k++) {
        int q = tid + k * 256;
        if (q < WINR) {
            int p = q + t0 - 6;
            stok[q] = ((unsigned)p < (unsigned)S) ? xr[p] : -1;
        }
    }
    __syncthreads();

    // ---- cooperative 8-lane T gather (4 rows per warp-instruction)
    const int col  = lane & 7;
    const int rsub = lane >> 3;
    #pragma unroll
    for (int j = 0; j < 17; j++) {
        int q = j * 32 + wid * 4 + rsub;     // 8 warps x 4 rows = 32/iter
        if (q < WINR) {
            int tok = stok[q];
            float v = (tok >= 0) ? g_T[(size_t)tok * 8 + col] : 0.f;
            if (col < 7) sTl[q * 7 + col] = v;
        }
    }
    __syncthreads();

    // ---- excitements (no bounds predicates: halo is zero)
    unsigned evu[3];
    #pragma unroll
    for (int k = 0; k < 3; k++) {
        int tl = tid + k * 256;              // local output index
        unsigned u = 0u;
        if (tl < len) {
            float s = 0.f;
            #pragma unroll
            for (int kw = 0; kw < 7; kw++) s += sTl[(tl + kw) * 7 + kw];
            u = fmono(s);
        }
        evu[k] = u;
    }

    // ---- warp-local top-8 via REDUX (value desc, global index asc on ties)
    #pragma unroll
    for (int r = 0; r < 8; r++) {
        unsigned bu = 0u; int bt = 0x7fffffff; int bk = 0;
        #pragma unroll
        for (int k = 0; k < 3; k++)
            if (evu[k] > bu) { bu = evu[k]; bt = t0 + tid + k * 256; bk = k; }
        unsigned m = __reduce_max_sync(FULL, bu);
        int tw = (bu == m) ? bt : 0x7fffffff;
        int tmin = __reduce_min_sync(FULL, tw);
        bool win = (bu == m) && (bt == tmin);
        #pragma unroll
        for (int k = 0; k < 3; k++)
            if (win && k == bk) evu[k] = 0u;
        if (lane == 0) { cu_s[wid * 8 + r] = m; ct_s[wid * 8 + r] = tmin; }
    }
    __syncthreads();

    // ---- warp 0 merges 64 -> segment top-8 (ordered), writes to gmem
    if (wid == 0) {
        unsigned cu[2]; int ct[2];
        #pragma unroll
        for (int j = 0; j < 2; j++) {
            cu[j] = cu_s[lane + 32 * j];
            ct[j] = ct_s[lane + 32 * j];
        }
        #pragma unroll
        for (int r = 0; r < 8; r++) {
            unsigned bu = 0u; int bt = 0x7fffffff; int bj = 0;
            #pragma unroll
            for (int j = 0; j < 2; j++)
                if (cu[j] > bu || (cu[j] == bu && ct[j] < bt)) {
                    bu = cu[j]; bt = ct[j]; bj = j;
                }
            unsigned m = __reduce_max_sync(FULL, bu);
            int tw = (bu == m) ? bt : 0x7fffffff;
            int tmin = __reduce_min_sync(FULL, tw);
            bool win = (bu == m) && (bt == tmin);
            #pragma unroll
            for (int j = 0; j < 2; j++)
                if (win && j == bj) cu[j] = 0u;
            if (lane == 0) {
                g_cand_u[row * 32 + seg * 8 + r] = m;
                g_cand_t[row * 32 + seg * 8 + r] = tmin;
            }
        }
    }
}

// ---------------------------------------------------------------------------
// Kernel B2: one CTA (256 thr) per row. Merge 32 candidates -> top-8,
// conv1 (8 warps), conv2/top4/dense (warp 0), fused last-CTA reduction.
// ---------------------------------------------------------------------------
__global__ void __launch_bounds__(256) tail_kernel(
    const int*   __restrict__ x,
    const float* __restrict__ emb,
    const float* __restrict__ W1, const float* __restrict__ b1,
    const float* __restrict__ W2, const float* __restrict__ b2,
    const float* __restrict__ Wd, const float* __restrict__ bd,
    float* __restrict__ out) {

    __shared__ float sW1[2100];
    __shared__ float s1p[96];       // 16x6 padded sigmoid(conv1)
    __shared__ float out2s[168];    // 12x14
    __shared__ int   idx8s[8];

    const int tid  = threadIdx.x;
    const int lane = tid & 31;
    const int wid  = tid >> 5;
    const int row  = blockIdx.x;
    const int* xr  = x + (size_t)row * S;

    // stage W1; zero s1p
    #pragma unroll
    for (int k = 0; k < 9; k++) {
        int i = tid + k * 256;
        if (i < 2100) sW1[i] = W1[i];
    }
    if (tid < 96) s1p[tid] = 0.f;

    // warp 0: merge 32 candidates (1 per lane) -> ordered global top-8
    if (wid == 0) {
        unsigned cu = g_cand_u[row * 32 + lane];
        int      ct = g_cand_t[row * 32 + lane];
        #pragma unroll
        for (int r = 0; r < 8; r++) {
            unsigned m = __reduce_max_sync(FULL, cu);
            int tw = (cu == m) ? ct : 0x7fffffff;
            int tmin = __reduce_min_sync(FULL, tw);
            if (lane == 0) idx8s[r] = tmin;
            if (cu == m && ct == tmin) cu = 0u;
        }
    }
    __syncthreads();

    // conv1 at the 8 selected positions: warp i -> position i
    {
        int pos = idx8s[wid];
        int tkn = -1;
        if (lane < 7) {
            int p = pos - 6 + lane;
            tkn = ((unsigned)p < (unsigned)S) ? xr[p] : -1;
        }
        float acc[6] = {0.f, 0.f, 0.f, 0.f, 0.f, 0.f};
        #pragma unroll
        for (int k = 0; k < 11; k++) {
            int rr = lane + 32 * k;
            bool ok = rr < 350;
            int rr2 = ok ? rr : 0;
            int kw = rr2 / 50;
            int cin = rr2 - kw * 50;
            int t = __shfl_sync(FULL, tkn, kw);
            float e = (ok && t >= 0) ? emb[(size_t)t * EMB + cin] : 0.f;
            #pragma unroll
            for (int c = 0; c < 6; c++) acc[c] += e * sW1[rr2 * 6 + c];
        }
        #pragma unroll
        for (int c = 0; c < 6; c++) {
            #pragma unroll
            for (int o = 16; o > 0; o >>= 1)
                acc[c] += __shfl_xor_sync(FULL, acc[c], o);   // all lanes: full sum
        }
        if (lane < 6) {
            float a = acc[0];
            a = (lane == 1) ? acc[1] : a;
            a = (lane == 2) ? acc[2] : a;
            a = (lane == 3) ? acc[3] : a;
            a = (lane == 4) ? acc[4] : a;
            a = (lane == 5) ? acc[5] : a;
            s1p[(4 + wid) * 6 + lane] = 1.f / (1.f + expf(-(a + b1[lane])));
        }
    }
    __syncthreads();

    // warp-0 tail: conv2 -> top4 -> mean -> dense -> last-row reduce
    if (wid == 0) {
        #pragma unroll
        for (int j = 0; j < 6; j++) {
            int idx = lane + 32 * j;
            if (idx < 168) {
                int t2 = idx / 14, c2 = idx - t2 * 14;
                float a = b2[c2];
                #pragma unroll
                for (int kw2 = 0; kw2 < 5; kw2++)
                    #pragma unroll
                    for (int cin = 0; cin < 6; cin++)
                        a += s1p[(t2 + kw2) * 6 + cin] * W2[(kw2 * 6 + cin) * 14 + c2];
                out2s[idx] = a;
            }
        }
        __syncwarp();
        float e2 = 0.f;
        if (lane < 12) {
            #pragma unroll
            for (int c = 0; c < 14; c++) e2 += out2s[lane * 14 + c];
        }
        unsigned e2u = (lane < 12) ? fmono(e2) : 0u;
        int j4r[4];
        #pragma unroll
        for (int r = 0; r < 4; r++) {
            unsigned m = __reduce_max_sync(FULL, e2u);
            int tw = (e2u == m) ? lane : 63;
            int tmin = __reduce_min_sync(FULL, tw);
            j4r[r] = tmin;
            if (lane == tmin) e2u = 0u;
        }
        float mm = 0.f;
        if (lane < 14)
            mm = 0.25f * (out2s[j4r[0] * 14 + lane] + out2s[j4r[1] * 14 + lane] +
                          out2s[j4r[2] * 14 + lane] + out2s[j4r[3] * 14 + lane]) * Wd[lane];
        #pragma unroll
        for (int o = 16; o > 0; o >>= 1) mm += __shfl_xor_sync(FULL, mm, o);

        unsigned old = 0;
        if (lane == 0) {
            g_part[row] = mm + bd[0];
            __threadfence();
            old = atomicInc(&g_ctr, B - 1);        // wraps -> self-reset each replay
        }
        old = __shfl_sync(FULL, old, 0);
        if (old == B - 1) {
            __threadfence();                       // acquire side
            float s = 0.f;
            #pragma unroll
            for (int k = 0; k < 8; k++) s += g_part[lane + 32 * k];
            #pragma unroll
            for (int o = 16; o > 0; o >>= 1) s += __shfl_xor_sync(FULL, s, o);
            if (lane == 0) out[0] = 1.f / (1.f + expf(-(s * (1.f / 256.f))));
        }
    }
}

// ---------------------------------------------------------------------------
extern "C" void kernel_launch(void* const* d_in, const int* in_sizes, int n_in,
                              void* d_out, int out_size) {
    const int*   x    = (const int*)  d_in[0];
    const float* emb  = (const float*)d_in[1];
    const float* W1   = (const float*)d_in[2];
    const float* b1   = (const float*)d_in[3];
    const float* W2   = (const float*)d_in[4];
    const float* b2   = (const float*)d_in[5];
    const float* Wd   = (const float*)d_in[6];
    const float* bd   = (const float*)d_in[7];
    float* out = (float*)d_out;

    buildT_kernel<<<(VOCAB + 127) / 128, 128>>>(emb, W1);
    topk_seg_kernel<<<4 * B, 256>>>(x);
    tail_kernel<<<B, 256>>>(x, emb, W1, b1, W2, b2, Wd, bd, out);
    (void)in_sizes; (void)n_in; (void)out_size;
}